// round 5
// baseline (speedup 1.0000x reference)
#include <cuda_runtime.h>
#include <cuda_bf16.h>
#include <math.h>
#include <stdint.h>

// ---------------------------------------------------------------------------
// ReDrafterHead: 2-layer GRU draft head + big vocab projection.
// B=64, HIDDEN=4096, DH=512, VOCAB=50257, NUM_DRAFT=4.
//
// Round 5: entire pre-logits chain fused into ONE persistent 128-CTA kernel
// (grid barrier via monotonic global counter; combine fused into GEMM
// epilogue; a_convert fused into layer-1 epilogue). 2 launches total.
// Logits GEMM unchanged (mma.sync bf16 hi/lo 3-term, round-4 proven).
// ---------------------------------------------------------------------------

#define B_      64
#define HID     4096
#define DH      512
#define VOCAB   50257
#define NDRAFT  4
#define GRIDN   128

// scratch (device globals; allocation in kernel_launch is forbidden)
__device__ float g_h[2][2][B_ * DH];        // [layer][slot][b*DH+j]
__device__ float g_part[16 * B_ * DH];      // ip split-K partials
__device__ __nv_bfloat16 g_Ahi[B_ * NDRAFT * DH];
__device__ __nv_bfloat16 g_Alo[B_ * NDRAFT * DH];
__device__ unsigned int g_bcount;           // monotonic barrier counter (never reset)

__device__ __forceinline__ float sigmoidf_(float v) { return 1.0f / (1.0f + __expf(-v)); }

__device__ __forceinline__ uint32_t pack_bf16x2(__nv_bfloat16 lo, __nv_bfloat16 hi) {
    return ((uint32_t)__bfloat16_as_ushort(hi) << 16) | (uint32_t)__bfloat16_as_ushort(lo);
}
__device__ __forceinline__ uint32_t smem_to_u32(const void* p) {
    uint32_t a;
    asm("{ .reg .u64 t; cvta.to.shared.u64 t, %1; cvt.u32.u64 %0, t; }" : "=r"(a) : "l"(p));
    return a;
}
__device__ __forceinline__ void ldsm4(uint32_t* r, uint32_t addr) {
    asm volatile("ldmatrix.sync.aligned.m8n8.x4.shared.b16 {%0,%1,%2,%3}, [%4];"
        : "=r"(r[0]), "=r"(r[1]), "=r"(r[2]), "=r"(r[3]) : "r"(addr));
}
__device__ __forceinline__ void mma16816(float* d, const uint32_t* a, const uint32_t* b) {
    asm volatile("mma.sync.aligned.m16n8k16.row.col.f32.bf16.bf16.f32 "
        "{%0,%1,%2,%3}, {%4,%5,%6,%7}, {%8,%9}, {%0,%1,%2,%3};"
        : "+f"(d[0]), "+f"(d[1]), "+f"(d[2]), "+f"(d[3])
        : "r"(a[0]), "r"(a[1]), "r"(a[2]), "r"(a[3]), "r"(b[0]), "r"(b[1]));
}

// Grid-wide barrier: monotonic counter, target = next multiple of GRIDN above
// my arrival index. Works across graph replays without reset (u32 wrap needs
// 33M kernel executions). Requires all GRIDN CTAs co-resident (wave-1).
__device__ __forceinline__ void grid_barrier(int tid) {
    __syncthreads();
    if (tid == 0) {
        __threadfence();
        unsigned int old = atomicAdd(&g_bcount, 1u);
        unsigned int target = (old / GRIDN + 1u) * GRIDN;
        unsigned int v;
        do {
            asm volatile("ld.acquire.gpu.global.u32 %0, [%1];" : "=r"(v) : "l"(&g_bcount));
        } while (v < target);
    }
    __syncthreads();
}

// ---------------------------------------------------------------------------
// Fused GRU kernel shared-memory layout
// ---------------------------------------------------------------------------
struct SmemIP { float As[32][64]; float Ws[32][64]; };
struct SmemG  { float A1[64][66]; float A2[64][66]; float W[24][66]; float epi[64][25]; };

// One GRU layer for one step: GEMM (64 x 24 x 512) + fused combine epilogue.
// CTA owns j-range [jb, jb+4); computes gate cols {r,z,n} x {ih,hh} at those j.
// a1mode: 0 = zeros (step 0 layer 0), 1 = embed gather, 2 = direct pointer.
__device__ __forceinline__ void gates_layer(
    SmemG& s, const int* sTid, int tid, int jb,
    int a1mode, const float* A1, const float* A2, const float* embed,
    const float* Wih, const float* Whh,
    const float* bih, const float* bhh,
    const float* hOld, float* hNew,
    __nv_bfloat16* ahi, __nv_bfloat16* alo, int step)
{
    const int mg = tid >> 3;     // 0..31 (row pair)
    const int gg = tid & 7;      // 0..7  (col group of 3)
    const int m0 = mg << 1;
    const int c0 = gg * 3;
    float acc[2][3] = {};
    const float (*As)[66] = (gg < 4) ? s.A1 : s.A2;

    for (int kt = 0; kt < DH; kt += 64) {
        // A1/A2 tiles: 64x64 each (4 float4 per thread per tile)
        #pragma unroll
        for (int i = 0; i < 4; i++) {
            int f = tid + i * 256;
            int row = f >> 4;
            int c4 = (f & 15) * 4;
            float4 v;
            if (a1mode == 0)      v = make_float4(0.f, 0.f, 0.f, 0.f);
            else if (a1mode == 1) v = *reinterpret_cast<const float4*>(
                                        &embed[(long)sTid[row] * DH + kt + c4]);
            else                  v = *reinterpret_cast<const float4*>(
                                        &A1[row * DH + kt + c4]);
            s.A1[row][c4 + 0] = v.x; s.A1[row][c4 + 1] = v.y;
            s.A1[row][c4 + 2] = v.z; s.A1[row][c4 + 3] = v.w;
            float4 u = *reinterpret_cast<const float4*>(&A2[row * DH + kt + c4]);
            s.A2[row][c4 + 0] = u.x; s.A2[row][c4 + 1] = u.y;
            s.A2[row][c4 + 2] = u.z; s.A2[row][c4 + 3] = u.w;
        }
        // W tile: 24 rows (12 w_ih + 12 w_hh) x 64 k
        #pragma unroll
        for (int i = 0; i < 2; i++) {
            int f = tid + i * 256;
            if (f < 384) {
                int r = f >> 4;
                int c4 = (f & 15) * 4;
                int rr = (r < 12) ? r : r - 12;
                const float* base = (r < 12) ? Wih : Whh;
                float4 v = *reinterpret_cast<const float4*>(
                    &base[((rr >> 2) * 512 + jb + (rr & 3)) * DH + kt + c4]);
                s.W[r][c4 + 0] = v.x; s.W[r][c4 + 1] = v.y;
                s.W[r][c4 + 2] = v.z; s.W[r][c4 + 3] = v.w;
            }
        }
        __syncthreads();
        #pragma unroll 8
        for (int k = 0; k < 64; k++) {
            float a0 = As[m0][k];
            float a1 = As[m0 + 1][k];
            float w0 = s.W[c0][k], w1 = s.W[c0 + 1][k], w2 = s.W[c0 + 2][k];
            acc[0][0] += a0 * w0; acc[0][1] += a0 * w1; acc[0][2] += a0 * w2;
            acc[1][0] += a1 * w0; acc[1][1] += a1 * w1; acc[1][2] += a1 * w2;
        }
        __syncthreads();
    }

    // stage gates to smem, then fused GRU combine (one (m, j) per thread)
    #pragma unroll
    for (int i = 0; i < 2; i++)
        #pragma unroll
        for (int j = 0; j < 3; j++)
            s.epi[m0 + i][c0 + j] = acc[i][j];
    __syncthreads();
    {
        int m = tid >> 2, j = tid & 3, jj = jb + j;
        float gir = s.epi[m][j],      giz = s.epi[m][4 + j],  gin = s.epi[m][8 + j];
        float ghr = s.epi[m][12 + j], ghz = s.epi[m][16 + j], ghn = s.epi[m][20 + j];
        float r = sigmoidf_(gir + bih[jj]       + ghr + bhh[jj]);
        float z = sigmoidf_(giz + bih[512 + jj] + ghz + bhh[512 + jj]);
        float n = tanhf(gin + bih[1024 + jj] + r * (ghn + bhh[1024 + jj]));
        float hnew = (1.f - z) * n + z * hOld[m * DH + jj];
        hNew[m * DH + jj] = hnew;
        if (ahi) {  // layer 1: fused a_convert (h2 -> bf16 hi/lo, m_out = b*4+step)
            int o = (m * NDRAFT + step) * DH + jj;
            __nv_bfloat16 hi = __float2bfloat16(hnew);
            ahi[o] = hi;
            alo[o] = __float2bfloat16(hnew - __bfloat162float(hi));
        }
    }
}

// ---------------------------------------------------------------------------
// Persistent fused kernel: ip proj + reduce + 4 x (2 GRU layers w/ combine)
// ---------------------------------------------------------------------------
__global__ __launch_bounds__(256) void gru_fused(
    const float* __restrict__ hidden, const int* __restrict__ tids,
    const float* __restrict__ ip_w,  const float* __restrict__ ip_b,
    const float* __restrict__ w_ih0, const float* __restrict__ w_hh0,
    const float* __restrict__ b_ih0, const float* __restrict__ b_hh0,
    const float* __restrict__ w_ih1, const float* __restrict__ w_hh1,
    const float* __restrict__ b_ih1, const float* __restrict__ b_hh1,
    const float* __restrict__ embed)
{
    __shared__ union { SmemIP ip; SmemG g; } sm;
    __shared__ int sTid[64];
    const int tid = threadIdx.x;
    const int c = blockIdx.x;

    // ---- phase 0: input projection partials (64x64 n-tile, 256-k slice) ----
    {
        const int n0 = (c & 7) * 64;
        const int kbase = (c >> 3) * 256;
        const int ty = tid >> 4, tx = tid & 15;
        float acc[4][4] = {};
        for (int kt = 0; kt < 256; kt += 32) {
            #pragma unroll
            for (int i = 0; i < 2; i++) {
                int f = tid + i * 256;
                int m = f >> 3;
                int kq = (f & 7) << 2;
                float4 va = *reinterpret_cast<const float4*>(&hidden[m * HID + kbase + kt + kq]);
                sm.ip.As[kq + 0][m] = va.x; sm.ip.As[kq + 1][m] = va.y;
                sm.ip.As[kq + 2][m] = va.z; sm.ip.As[kq + 3][m] = va.w;
                float4 vw = *reinterpret_cast<const float4*>(&ip_w[(n0 + m) * HID + kbase + kt + kq]);
                sm.ip.Ws[kq + 0][m] = vw.x; sm.ip.Ws[kq + 1][m] = vw.y;
                sm.ip.Ws[kq + 2][m] = vw.z; sm.ip.Ws[kq + 3][m] = vw.w;
            }
            __syncthreads();
            #pragma unroll
            for (int kk = 0; kk < 32; kk++) {
                float a[4], b[4];
                #pragma unroll
                for (int i = 0; i < 4; i++) { a[i] = sm.ip.As[kk][ty * 4 + i]; b[i] = sm.ip.Ws[kk][tx * 4 + i]; }
                #pragma unroll
                for (int i = 0; i < 4; i++)
                    #pragma unroll
                    for (int j = 0; j < 4; j++) acc[i][j] += a[i] * b[j];
            }
            __syncthreads();
        }
        float* part = g_part + (c >> 3) * (B_ * DH);
        #pragma unroll
        for (int i = 0; i < 4; i++)
            #pragma unroll
            for (int j = 0; j < 4; j++)
                part[(ty * 4 + i) * DH + n0 + tx * 4 + j] = acc[i][j];
    }
    grid_barrier(tid);

    // ---- phase 1: reduce 16 partials + bias -> h0 into slot 0 of both layers
    {
        int idx = c * 256 + tid;     // exactly 32768 threads
        float s = 0.f;
        #pragma unroll
        for (int p = 0; p < 16; p++) s += g_part[p * (B_ * DH) + idx];
        s += ip_b[idx & (DH - 1)];
        g_h[0][0][idx] = s;
        g_h[1][0][idx] = s;
    }
    grid_barrier(tid);

    // ---- phases 2..9: 4 draft steps x 2 GRU layers ----
    const int jb = c * 4;
    for (int step = 0; step < NDRAFT; step++) {
        const int p = step & 1;
        // layer 0: gi = x @ w_ih0.T, gh = hA @ w_hh0.T
        if (step > 0 && tid < 64) sTid[tid] = tids[tid * NDRAFT + step - 1];
        __syncthreads();
        gates_layer(sm.g, sTid, tid, jb,
                    (step == 0) ? 0 : 1, nullptr, g_h[0][p], embed,
                    w_ih0, w_hh0, b_ih0, b_hh0,
                    g_h[0][p], g_h[0][1 - p], nullptr, nullptr, step);
        grid_barrier(tid);
        // layer 1: gi = h1 @ w_ih1.T, gh = hB @ w_hh1.T; epilogue writes Ahi/Alo
        gates_layer(sm.g, sTid, tid, jb,
                    2, g_h[0][1 - p], g_h[1][p], embed,
                    w_ih1, w_hh1, b_ih1, b_hh1,
                    g_h[1][p], g_h[1][1 - p], g_Ahi, g_Alo, step);
        grid_barrier(tid);
    }
}

// ---------------------------------------------------------------------------
// Logits GEMM via mma.sync (bf16 hi/lo 3-MMA split, fp32 accum) — round-4.
// out[m, v] = sum_k h2[m,k] * out_w[v,k].  M=256, N=50257, K=512.
// CTA tile 128x128x32, 8 warps (2 M x 4 N), warp tile 64x32.
// ---------------------------------------------------------------------------
#define ROWB 80
#define AHI_OFF(s) ((s) * 10240)
#define ALO_OFF(s) (20480 + (s) * 10240)
#define BHI_OFF(s) (40960 + (s) * 10240)
#define BLO_OFF(s) (61440 + (s) * 10240)
#define LOGITS_SMEM 81920

__global__ __launch_bounds__(256, 1) void logits_mma(const float* __restrict__ W,
                                                     float* __restrict__ out)
{
    extern __shared__ char smem[];
    const uint32_t sbase = smem_to_u32(smem);
    const int tid  = threadIdx.x;
    const int lane = tid & 31;
    const int w    = tid >> 5;
    const int wm   = w >> 2;
    const int wn   = w & 3;
    const int n0   = blockIdx.x * 128;
    const int m0   = blockIdx.y * 128;

    float d[4][4][4];
    #pragma unroll
    for (int i = 0; i < 4; i++)
        #pragma unroll
        for (int j = 0; j < 4; j++)
            #pragma unroll
            for (int q = 0; q < 4; q++) d[i][j][q] = 0.f;

    float4 breg[4];

    auto cpasync_A = [&](int c, int s) {
        const int k0 = c * 32;
        #pragma unroll
        for (int i = 0; i < 2; i++) {
            int idx = tid + i * 256;
            int row = idx >> 2;
            int ch  = idx & 3;
            const __nv_bfloat16* sh = &g_Ahi[(m0 + row) * DH + k0 + ch * 8];
            uint32_t dh = sbase + AHI_OFF(s) + row * ROWB + ch * 16;
            asm volatile("cp.async.ca.shared.global [%0], [%1], 16;" :: "r"(dh), "l"(sh));
            const __nv_bfloat16* sl = &g_Alo[(m0 + row) * DH + k0 + ch * 8];
            uint32_t dl = sbase + ALO_OFF(s) + row * ROWB + ch * 16;
            asm volatile("cp.async.ca.shared.global [%0], [%1], 16;" :: "r"(dl), "l"(sl));
        }
        asm volatile("cp.async.commit_group;" ::: "memory");
    };

    auto ldg_B = [&](int c) {
        const int k0 = c * 32;
        #pragma unroll
        for (int i = 0; i < 4; i++) {
            int idx = tid + i * 256;
            int row = idx >> 3;
            int col = (idx & 7) * 4;
            int vr = n0 + row;
            breg[i] = (vr < VOCAB)
                ? *reinterpret_cast<const float4*>(&W[(long)vr * DH + k0 + col])
                : make_float4(0.f, 0.f, 0.f, 0.f);
        }
    };

    auto sts_B = [&](int s) {
        #pragma unroll
        for (int i = 0; i < 4; i++) {
            int idx = tid + i * 256;
            int row = idx >> 3;
            int col = (idx & 7) * 4;
            float4 v = breg[i];
            __nv_bfloat16 hx = __float2bfloat16(v.x), hy = __float2bfloat16(v.y);
            __nv_bfloat16 hz = __float2bfloat16(v.z), hw = __float2bfloat16(v.w);
            __nv_bfloat16 lx = __float2bfloat16(v.x - __bfloat162float(hx));
            __nv_bfloat16 ly = __float2bfloat16(v.y - __bfloat162float(hy));
            __nv_bfloat16 lz = __float2bfloat16(v.z - __bfloat162float(hz));
            __nv_bfloat16 lw = __float2bfloat16(v.w - __bfloat162float(hw));
            uint2 ph, pl;
            ph.x = pack_bf16x2(hx, hy); ph.y = pack_bf16x2(hz, hw);
            pl.x = pack_bf16x2(lx, ly); pl.y = pack_bf16x2(lz, lw);
            *reinterpret_cast<uint2*>(smem + BHI_OFF(s) + row * ROWB + col * 2) = ph;
            *reinterpret_cast<uint2*>(smem + BLO_OFF(s) + row * ROWB + col * 2) = pl;
        }
    };

    auto compute = [&](int s) {
        #pragma unroll
        for (int ks = 0; ks < 2; ks++) {
            uint32_t ah[4][4], al[4][4];
            #pragma unroll
            for (int mi = 0; mi < 4; mi++) {
                int row = wm * 64 + mi * 16 + (lane & 15);
                int kc  = ks * 32 + (lane >> 4) * 16;
                ldsm4(ah[mi], sbase + AHI_OFF(s) + row * ROWB + kc);
                ldsm4(al[mi], sbase + ALO_OFF(s) + row * ROWB + kc);
            }
            uint32_t bh[4][2], bl[4][2];
            #pragma unroll
            for (int nb2 = 0; nb2 < 2; nb2++) {
                int g   = lane >> 3;
                int row = wn * 32 + nb2 * 16 + (g >> 1) * 8 + (lane & 7);
                int kc  = ks * 32 + (g & 1) * 16;
                ldsm4(&bh[nb2 * 2][0], sbase + BHI_OFF(s) + row * ROWB + kc);
                ldsm4(&bl[nb2 * 2][0], sbase + BLO_OFF(s) + row * ROWB + kc);
            }
            #pragma unroll
            for (int mi = 0; mi < 4; mi++)
                #pragma unroll
                for (int ni = 0; ni < 4; ni++) {
                    mma16816(d[mi][ni], ah[mi], bh[ni]);
                    mma16816(d[mi][ni], ah[mi], bl[ni]);
                    mma16816(d[mi][ni], al[mi], bh[ni]);
                }
        }
    };

    cpasync_A(0, 0);
    ldg_B(0);
    sts_B(0);
    asm volatile("cp.async.wait_group 0;" ::: "memory");
    __syncthreads();

    #pragma unroll 1
    for (int c = 0; c < 16; c++) {
        int s = c & 1;
        if (c + 1 < 16) {
            cpasync_A(c + 1, 1 - s);
            ldg_B(c + 1);
        }
        compute(s);
        if (c + 1 < 16) {
            sts_B(1 - s);
            asm volatile("cp.async.wait_group 0;" ::: "memory");
        }
        __syncthreads();
    }

    const int g  = lane >> 2;
    const int i2 = (lane & 3) * 2;
    #pragma unroll
    for (int mi = 0; mi < 4; mi++) {
        int r0 = m0 + wm * 64 + mi * 16 + g;
        long rb0 = (long)r0 * VOCAB;
        long rb1 = (long)(r0 + 8) * VOCAB;
        #pragma unroll
        for (int ni = 0; ni < 4; ni++) {
            int col = n0 + wn * 32 + ni * 8 + i2;
            if (col < VOCAB) {
                out[rb0 + col] = d[mi][ni][0];
                out[rb1 + col] = d[mi][ni][2];
                if (col + 1 < VOCAB) {
                    out[rb0 + col + 1] = d[mi][ni][1];
                    out[rb1 + col + 1] = d[mi][ni][3];
                }
            }
        }
    }
}

// ---------------------------------------------------------------------------
extern "C" void kernel_launch(void* const* d_in, const int* in_sizes, int n_in,
                              void* d_out, int out_size)
{
    const float* hidden = (const float*)d_in[0];
    const int*   tids   = (const int*)  d_in[1];
    const float* ip_w   = (const float*)d_in[2];
    const float* ip_b   = (const float*)d_in[3];
    const float* w_ih0  = (const float*)d_in[4];
    const float* w_hh0  = (const float*)d_in[5];
    const float* b_ih0  = (const float*)d_in[6];
    const float* b_hh0  = (const float*)d_in[7];
    const float* w_ih1  = (const float*)d_in[8];
    const float* w_hh1  = (const float*)d_in[9];
    const float* b_ih1  = (const float*)d_in[10];
    const float* b_hh1  = (const float*)d_in[11];
    const float* embed  = (const float*)d_in[12];
    const float* out_w  = (const float*)d_in[13];
    float* out = (float*)d_out;

    cudaFuncSetAttribute(logits_mma, cudaFuncAttributeMaxDynamicSharedMemorySize, LOGITS_SMEM);

    // fused: ip proj + 4 x (GRU layer0 + layer1, combine in epilogue) + bf16 split
    gru_fused<<<GRIDN, 256>>>(hidden, tids, ip_w, ip_b,
                              w_ih0, w_hh0, b_ih0, b_hh0,
                              w_ih1, w_hh1, b_ih1, b_hh1, embed);

    // batched vocab projection over all 4 steps
    logits_mma<<<dim3((VOCAB + 127) / 128, 2), 256, LOGITS_SMEM>>>(out_w, out);
}

// round 6
// speedup vs baseline: 1.1225x; 1.1225x over previous
#include <cuda_runtime.h>
#include <cuda_bf16.h>
#include <math.h>
#include <stdint.h>

// ---------------------------------------------------------------------------
// ReDrafterHead: 2-layer GRU draft head + big vocab projection.
// B=64, HIDDEN=4096, DH=512, VOCAB=50257, NUM_DRAFT=4.
//
// Round 6:
//  - gru_fused compute rewritten: float4 dot-product inner loop, 4x3 utile,
//    128 compute threads (FFMA-floor bound), 256 loader threads.
//  - logits_mma: N-tile 64, warp tile 64x16, <=128 regs, 2 CTAs/SM.
// ---------------------------------------------------------------------------

#define B_      64
#define HID     4096
#define DH      512
#define VOCAB   50257
#define NDRAFT  4
#define GRIDN   128

__device__ float g_h[2][2][B_ * DH];        // [layer][slot][b*DH+j]
__device__ float g_part[16 * B_ * DH];      // ip split-K partials
__device__ __nv_bfloat16 g_Ahi[B_ * NDRAFT * DH];
__device__ __nv_bfloat16 g_Alo[B_ * NDRAFT * DH];
__device__ unsigned int g_bcount;           // monotonic barrier counter

__device__ __forceinline__ float sigmoidf_(float v) { return 1.0f / (1.0f + __expf(-v)); }

__device__ __forceinline__ uint32_t pack_bf16x2(__nv_bfloat16 lo, __nv_bfloat16 hi) {
    return ((uint32_t)__bfloat16_as_ushort(hi) << 16) | (uint32_t)__bfloat16_as_ushort(lo);
}
__device__ __forceinline__ uint32_t smem_to_u32(const void* p) {
    uint32_t a;
    asm("{ .reg .u64 t; cvta.to.shared.u64 t, %1; cvt.u32.u64 %0, t; }" : "=r"(a) : "l"(p));
    return a;
}
__device__ __forceinline__ void ldsm4(uint32_t* r, uint32_t addr) {
    asm volatile("ldmatrix.sync.aligned.m8n8.x4.shared.b16 {%0,%1,%2,%3}, [%4];"
        : "=r"(r[0]), "=r"(r[1]), "=r"(r[2]), "=r"(r[3]) : "r"(addr));
}
__device__ __forceinline__ void mma16816(float* d, const uint32_t* a, const uint32_t* b) {
    asm volatile("mma.sync.aligned.m16n8k16.row.col.f32.bf16.bf16.f32 "
        "{%0,%1,%2,%3}, {%4,%5,%6,%7}, {%8,%9}, {%0,%1,%2,%3};"
        : "+f"(d[0]), "+f"(d[1]), "+f"(d[2]), "+f"(d[3])
        : "r"(a[0]), "r"(a[1]), "r"(a[2]), "r"(a[3]), "r"(b[0]), "r"(b[1]));
}

// Grid-wide barrier: monotonic counter (graph-replay safe; GRIDN co-resident).
__device__ __forceinline__ void grid_barrier(int tid) {
    __syncthreads();
    if (tid == 0) {
        __threadfence();
        unsigned int old = atomicAdd(&g_bcount, 1u);
        unsigned int target = (old / GRIDN + 1u) * GRIDN;
        unsigned int v;
        do {
            asm volatile("ld.acquire.gpu.global.u32 %0, [%1];" : "=r"(v) : "l"(&g_bcount));
        } while (v < target);
    }
    __syncthreads();
}

// ---------------------------------------------------------------------------
struct SmemIP { float As[32][64]; float Ws[32][64]; };
struct SmemG  { float A1[64][68]; float A2[64][68]; float W[24][68]; float epi[64][25]; };

// One GRU layer for one step. CTA owns j-range [jb, jb+4): GEMM 64 x 24 x 512
// (cols 0-11: gi {r,z,n} x 4j via Wih; cols 12-23: gh via Whh) + fused combine.
// a1mode: 0 = zeros, 1 = embed gather, 2 = pointer.
__device__ __forceinline__ void gates_layer(
    SmemG& s, const int* sTid, int tid, int jb,
    int a1mode, const float* A1g, const float* A2g, const float* embed,
    const float* Wih, const float* Whh,
    const float* bih, const float* bhh,
    const float* hOld, float* hNew,
    __nv_bfloat16* ahi, __nv_bfloat16* alo, int step)
{
    const bool active = tid < 128;
    const int m0 = ((tid >> 3) & 15) * 4;   // 0..60
    const int g  = tid & 7;                 // 0..7
    const int c0 = g * 3;                   // 0..21
    float acc[4][3] = {};
    const float (*As)[68] = (g < 4) ? s.A1 : s.A2;

    for (int kt = 0; kt < DH; kt += 64) {
        // A1/A2 tiles 64x64 (4 float4 per thread each)
        #pragma unroll
        for (int i = 0; i < 4; i++) {
            int f = tid + i * 256;
            int row = f >> 4;
            int c4  = (f & 15) * 4;
            float4 v;
            if (a1mode == 0)      v = make_float4(0.f, 0.f, 0.f, 0.f);
            else if (a1mode == 1) v = *reinterpret_cast<const float4*>(
                                        &embed[(long)sTid[row] * DH + kt + c4]);
            else                  v = *reinterpret_cast<const float4*>(
                                        &A1g[row * DH + kt + c4]);
            *reinterpret_cast<float4*>(&s.A1[row][c4]) = v;
            *reinterpret_cast<float4*>(&s.A2[row][c4]) =
                *reinterpret_cast<const float4*>(&A2g[row * DH + kt + c4]);
        }
        // W tile: 24 rows (12 Wih + 12 Whh) x 64
        #pragma unroll
        for (int i = 0; i < 2; i++) {
            int f = tid + i * 256;
            if (f < 384) {
                int r = f >> 4;
                int c4 = (f & 15) * 4;
                int rr = (r < 12) ? r : r - 12;
                const float* base = (r < 12) ? Wih : Whh;
                *reinterpret_cast<float4*>(&s.W[r][c4]) =
                    *reinterpret_cast<const float4*>(
                        &base[((rr >> 2) * 512 + jb + (rr & 3)) * DH + kt + c4]);
            }
        }
        __syncthreads();
        if (active) {
            #pragma unroll 4
            for (int k = 0; k < 64; k += 4) {
                float4 w0 = *reinterpret_cast<const float4*>(&s.W[c0 + 0][k]);
                float4 w1 = *reinterpret_cast<const float4*>(&s.W[c0 + 1][k]);
                float4 w2 = *reinterpret_cast<const float4*>(&s.W[c0 + 2][k]);
                #pragma unroll
                for (int i = 0; i < 4; i++) {
                    float4 a = *reinterpret_cast<const float4*>(&As[m0 + i][k]);
                    acc[i][0] += a.x * w0.x + a.y * w0.y + a.z * w0.z + a.w * w0.w;
                    acc[i][1] += a.x * w1.x + a.y * w1.y + a.z * w1.z + a.w * w1.w;
                    acc[i][2] += a.x * w2.x + a.y * w2.y + a.z * w2.z + a.w * w2.w;
                }
            }
        }
        __syncthreads();
    }

    if (active) {
        #pragma unroll
        for (int i = 0; i < 4; i++)
            #pragma unroll
            for (int j = 0; j < 3; j++)
                s.epi[m0 + i][c0 + j] = acc[i][j];
    }
    __syncthreads();
    {
        int m = tid >> 2, j = tid & 3, jj = jb + j;
        float gir = s.epi[m][j],      giz = s.epi[m][4 + j],  gin = s.epi[m][8 + j];
        float ghr = s.epi[m][12 + j], ghz = s.epi[m][16 + j], ghn = s.epi[m][20 + j];
        float r = sigmoidf_(gir + bih[jj]       + ghr + bhh[jj]);
        float z = sigmoidf_(giz + bih[512 + jj] + ghz + bhh[512 + jj]);
        float n = tanhf(gin + bih[1024 + jj] + r * (ghn + bhh[1024 + jj]));
        float hnew = (1.f - z) * n + z * hOld[m * DH + jj];
        hNew[m * DH + jj] = hnew;
        if (ahi) {
            int o = (m * NDRAFT + step) * DH + jj;
            __nv_bfloat16 hi = __float2bfloat16(hnew);
            ahi[o] = hi;
            alo[o] = __float2bfloat16(hnew - __bfloat162float(hi));
        }
    }
}

// ---------------------------------------------------------------------------
__global__ __launch_bounds__(256) void gru_fused(
    const float* __restrict__ hidden, const int* __restrict__ tids,
    const float* __restrict__ ip_w,  const float* __restrict__ ip_b,
    const float* __restrict__ w_ih0, const float* __restrict__ w_hh0,
    const float* __restrict__ b_ih0, const float* __restrict__ b_hh0,
    const float* __restrict__ w_ih1, const float* __restrict__ w_hh1,
    const float* __restrict__ b_ih1, const float* __restrict__ b_hh1,
    const float* __restrict__ embed)
{
    __shared__ union { SmemIP ip; SmemG g; } sm;
    __shared__ int sTid[64];
    const int tid = threadIdx.x;
    const int c = blockIdx.x;

    // ---- phase 0: input projection partials (64x64 n-tile, 256-k slice) ----
    {
        const int n0 = (c & 7) * 64;
        const int kbase = (c >> 3) * 256;
        const int ty = tid >> 4, tx = tid & 15;
        float acc[4][4] = {};
        for (int kt = 0; kt < 256; kt += 32) {
            #pragma unroll
            for (int i = 0; i < 2; i++) {
                int f = tid + i * 256;
                int m = f >> 3;
                int kq = (f & 7) << 2;
                float4 va = *reinterpret_cast<const float4*>(&hidden[m * HID + kbase + kt + kq]);
                sm.ip.As[kq + 0][m] = va.x; sm.ip.As[kq + 1][m] = va.y;
                sm.ip.As[kq + 2][m] = va.z; sm.ip.As[kq + 3][m] = va.w;
                float4 vw = *reinterpret_cast<const float4*>(&ip_w[(n0 + m) * HID + kbase + kt + kq]);
                sm.ip.Ws[kq + 0][m] = vw.x; sm.ip.Ws[kq + 1][m] = vw.y;
                sm.ip.Ws[kq + 2][m] = vw.z; sm.ip.Ws[kq + 3][m] = vw.w;
            }
            __syncthreads();
            #pragma unroll
            for (int kk = 0; kk < 32; kk++) {
                float a[4], b[4];
                #pragma unroll
                for (int i = 0; i < 4; i++) { a[i] = sm.ip.As[kk][ty * 4 + i]; b[i] = sm.ip.Ws[kk][tx * 4 + i]; }
                #pragma unroll
                for (int i = 0; i < 4; i++)
                    #pragma unroll
                    for (int j = 0; j < 4; j++) acc[i][j] += a[i] * b[j];
            }
            __syncthreads();
        }
        float* part = g_part + (c >> 3) * (B_ * DH);
        #pragma unroll
        for (int i = 0; i < 4; i++)
            #pragma unroll
            for (int j = 0; j < 4; j++)
                part[(ty * 4 + i) * DH + n0 + tx * 4 + j] = acc[i][j];
    }
    grid_barrier(tid);

    // ---- phase 1: reduce 16 partials + bias ----
    {
        int idx = c * 256 + tid;
        float s = 0.f;
        #pragma unroll
        for (int p = 0; p < 16; p++) s += g_part[p * (B_ * DH) + idx];
        s += ip_b[idx & (DH - 1)];
        g_h[0][0][idx] = s;
        g_h[1][0][idx] = s;
    }
    grid_barrier(tid);

    // ---- 4 draft steps x 2 GRU layers ----
    const int jb = c * 4;
    for (int step = 0; step < NDRAFT; step++) {
        const int p = step & 1;
        if (step > 0 && tid < 64) sTid[tid] = tids[tid * NDRAFT + step - 1];
        __syncthreads();
        gates_layer(sm.g, sTid, tid, jb,
                    (step == 0) ? 0 : 1, nullptr, g_h[0][p], embed,
                    w_ih0, w_hh0, b_ih0, b_hh0,
                    g_h[0][p], g_h[0][1 - p], nullptr, nullptr, step);
        grid_barrier(tid);
        gates_layer(sm.g, sTid, tid, jb,
                    2, g_h[0][1 - p], g_h[1][p], embed,
                    w_ih1, w_hh1, b_ih1, b_hh1,
                    g_h[1][p], g_h[1][1 - p], g_Ahi, g_Alo, step);
        grid_barrier(tid);
    }
}

// ---------------------------------------------------------------------------
// Logits GEMM via mma.sync (bf16 hi/lo 3-MMA split, fp32 accum).
// CTA tile 128(M) x 64(N) x 32(K); 8 warps (2 M x 4 N); warp tile 64x16.
// <=128 regs, 2 CTAs/SM. grid (786, 2).
// ---------------------------------------------------------------------------
#define ROWB 80
#define AHI_OFF(s) ((s) * 10240)
#define ALO_OFF(s) (20480 + (s) * 10240)
#define BHI_OFF(s) (40960 + (s) * 5120)
#define BLO_OFF(s) (51200 + (s) * 5120)
#define LOGITS_SMEM 61440

__global__ __launch_bounds__(256, 2) void logits_mma(const float* __restrict__ W,
                                                     float* __restrict__ out)
{
    extern __shared__ char smem[];
    const uint32_t sbase = smem_to_u32(smem);
    const int tid  = threadIdx.x;
    const int lane = tid & 31;
    const int w    = tid >> 5;
    const int wm   = w >> 2;   // 0..1
    const int wn   = w & 3;    // 0..3
    const int n0   = blockIdx.x * 64;
    const int m0   = blockIdx.y * 128;

    float d[4][2][4];
    #pragma unroll
    for (int i = 0; i < 4; i++)
        #pragma unroll
        for (int j = 0; j < 2; j++)
            #pragma unroll
            for (int q = 0; q < 4; q++) d[i][j][q] = 0.f;

    float4 breg[2];

    auto cpasync_A = [&](int c, int s) {
        const int k0 = c * 32;
        #pragma unroll
        for (int i = 0; i < 2; i++) {
            int idx = tid + i * 256;
            int row = idx >> 2;
            int ch  = idx & 3;
            const __nv_bfloat16* sh = &g_Ahi[(m0 + row) * DH + k0 + ch * 8];
            uint32_t dh = sbase + AHI_OFF(s) + row * ROWB + ch * 16;
            asm volatile("cp.async.ca.shared.global [%0], [%1], 16;" :: "r"(dh), "l"(sh));
            const __nv_bfloat16* sl = &g_Alo[(m0 + row) * DH + k0 + ch * 8];
            uint32_t dl = sbase + ALO_OFF(s) + row * ROWB + ch * 16;
            asm volatile("cp.async.ca.shared.global [%0], [%1], 16;" :: "r"(dl), "l"(sl));
        }
        asm volatile("cp.async.commit_group;" ::: "memory");
    };

    auto ldg_B = [&](int c) {
        const int k0 = c * 32;
        #pragma unroll
        for (int i = 0; i < 2; i++) {
            int idx = tid + i * 256;
            int row = idx >> 3;              // 0..63
            int col = (idx & 7) * 4;
            int vr = n0 + row;
            breg[i] = (vr < VOCAB)
                ? *reinterpret_cast<const float4*>(&W[(long)vr * DH + k0 + col])
                : make_float4(0.f, 0.f, 0.f, 0.f);
        }
    };

    auto sts_B = [&](int s) {
        #pragma unroll
        for (int i = 0; i < 2; i++) {
            int idx = tid + i * 256;
            int row = idx >> 3;
            int col = (idx & 7) * 4;
            float4 v = breg[i];
            __nv_bfloat16 hx = __float2bfloat16(v.x), hy = __float2bfloat16(v.y);
            __nv_bfloat16 hz = __float2bfloat16(v.z), hw = __float2bfloat16(v.w);
            __nv_bfloat16 lx = __float2bfloat16(v.x - __bfloat162float(hx));
            __nv_bfloat16 ly = __float2bfloat16(v.y - __bfloat162float(hy));
            __nv_bfloat16 lz = __float2bfloat16(v.z - __bfloat162float(hz));
            __nv_bfloat16 lw = __float2bfloat16(v.w - __bfloat162float(hw));
            uint2 ph, pl;
            ph.x = pack_bf16x2(hx, hy); ph.y = pack_bf16x2(hz, hw);
            pl.x = pack_bf16x2(lx, ly); pl.y = pack_bf16x2(lz, lw);
            *reinterpret_cast<uint2*>(smem + BHI_OFF(s) + row * ROWB + col * 2) = ph;
            *reinterpret_cast<uint2*>(smem + BLO_OFF(s) + row * ROWB + col * 2) = pl;
        }
    };

    auto compute = [&](int s) {
        #pragma unroll
        for (int ks = 0; ks < 2; ks++) {
            uint32_t ah[4][4], al[4][4];
            #pragma unroll
            for (int mi = 0; mi < 4; mi++) {
                int row = wm * 64 + mi * 16 + (lane & 15);
                int kc  = ks * 32 + (lane >> 4) * 16;
                ldsm4(ah[mi], sbase + AHI_OFF(s) + row * ROWB + kc);
                ldsm4(al[mi], sbase + ALO_OFF(s) + row * ROWB + kc);
            }
            uint32_t bh[2][2], bl[2][2];
            {
                int gq  = lane >> 3;
                int row = wn * 16 + (gq >> 1) * 8 + (lane & 7);
                int kc  = ks * 32 + (gq & 1) * 16;
                ldsm4(&bh[0][0], sbase + BHI_OFF(s) + row * ROWB + kc);
                ldsm4(&bl[0][0], sbase + BLO_OFF(s) + row * ROWB + kc);
            }
            #pragma unroll
            for (int mi = 0; mi < 4; mi++)
                #pragma unroll
                for (int ni = 0; ni < 2; ni++) {
                    mma16816(d[mi][ni], ah[mi], bh[ni]);
                    mma16816(d[mi][ni], ah[mi], bl[ni]);
                    mma16816(d[mi][ni], al[mi], bh[ni]);
                }
        }
    };

    cpasync_A(0, 0);
    ldg_B(0);
    sts_B(0);
    asm volatile("cp.async.wait_group 0;" ::: "memory");
    __syncthreads();

    #pragma unroll 1
    for (int c = 0; c < 16; c++) {
        int s = c & 1;
        if (c + 1 < 16) {
            cpasync_A(c + 1, 1 - s);
            ldg_B(c + 1);
        }
        compute(s);
        if (c + 1 < 16) {
            sts_B(1 - s);
            asm volatile("cp.async.wait_group 0;" ::: "memory");
        }
        __syncthreads();
    }

    const int g  = lane >> 2;
    const int i2 = (lane & 3) * 2;
    #pragma unroll
    for (int mi = 0; mi < 4; mi++) {
        int r0 = m0 + wm * 64 + mi * 16 + g;
        long rb0 = (long)r0 * VOCAB;
        long rb1 = (long)(r0 + 8) * VOCAB;
        #pragma unroll
        for (int ni = 0; ni < 2; ni++) {
            int col = n0 + wn * 16 + ni * 8 + i2;
            if (col < VOCAB) {
                out[rb0 + col] = d[mi][ni][0];
                out[rb1 + col] = d[mi][ni][2];
                if (col + 1 < VOCAB) {
                    out[rb0 + col + 1] = d[mi][ni][1];
                    out[rb1 + col + 1] = d[mi][ni][3];
                }
            }
        }
    }
}

// ---------------------------------------------------------------------------
extern "C" void kernel_launch(void* const* d_in, const int* in_sizes, int n_in,
                              void* d_out, int out_size)
{
    const float* hidden = (const float*)d_in[0];
    const int*   tids   = (const int*)  d_in[1];
    const float* ip_w   = (const float*)d_in[2];
    const float* ip_b   = (const float*)d_in[3];
    const float* w_ih0  = (const float*)d_in[4];
    const float* w_hh0  = (const float*)d_in[5];
    const float* b_ih0  = (const float*)d_in[6];
    const float* b_hh0  = (const float*)d_in[7];
    const float* w_ih1  = (const float*)d_in[8];
    const float* w_hh1  = (const float*)d_in[9];
    const float* b_ih1  = (const float*)d_in[10];
    const float* b_hh1  = (const float*)d_in[11];
    const float* embed  = (const float*)d_in[12];
    const float* out_w  = (const float*)d_in[13];
    float* out = (float*)d_out;

    cudaFuncSetAttribute(logits_mma, cudaFuncAttributeMaxDynamicSharedMemorySize, LOGITS_SMEM);

    gru_fused<<<GRIDN, 256>>>(hidden, tids, ip_w, ip_b,
                              w_ih0, w_hh0, b_ih0, b_hh0,
                              w_ih1, w_hh1, b_ih1, b_hh1, embed);

    logits_mma<<<dim3((VOCAB + 63) / 64, 2), 256, LOGITS_SMEM>>>(out_w, out);
}

// round 7
// speedup vs baseline: 1.2878x; 1.1472x over previous
#include <cuda_runtime.h>
#include <cuda_bf16.h>
#include <math.h>
#include <stdint.h>

// ---------------------------------------------------------------------------
// ReDrafterHead: 2-layer GRU draft head + big vocab projection.
// B=64, HIDDEN=4096, DH=512, VOCAB=50257, NUM_DRAFT=4.
//
// Round 7:
//  - gates_layer: conflict-free LDS banks, 256 compute threads (2x3 utile),
//    register-prefetch pipeline over 32-wide k-tiles.
//  - logits_mma: grid (2, 786) so m-half pairs co-schedule (B L2 reuse).
// ---------------------------------------------------------------------------

#define B_      64
#define HID     4096
#define DH      512
#define VOCAB   50257
#define NDRAFT  4
#define GRIDN   128

__device__ float g_h[2][2][B_ * DH];        // [layer][slot][b*DH+j]
__device__ float g_part[16 * B_ * DH];      // ip split-K partials
__device__ __nv_bfloat16 g_Ahi[B_ * NDRAFT * DH];
__device__ __nv_bfloat16 g_Alo[B_ * NDRAFT * DH];
__device__ unsigned int g_bcount;           // monotonic barrier counter

__device__ __forceinline__ float sigmoidf_(float v) { return 1.0f / (1.0f + __expf(-v)); }

__device__ __forceinline__ uint32_t pack_bf16x2(__nv_bfloat16 lo, __nv_bfloat16 hi) {
    return ((uint32_t)__bfloat16_as_ushort(hi) << 16) | (uint32_t)__bfloat16_as_ushort(lo);
}
__device__ __forceinline__ uint32_t smem_to_u32(const void* p) {
    uint32_t a;
    asm("{ .reg .u64 t; cvta.to.shared.u64 t, %1; cvt.u32.u64 %0, t; }" : "=r"(a) : "l"(p));
    return a;
}
__device__ __forceinline__ void ldsm4(uint32_t* r, uint32_t addr) {
    asm volatile("ldmatrix.sync.aligned.m8n8.x4.shared.b16 {%0,%1,%2,%3}, [%4];"
        : "=r"(r[0]), "=r"(r[1]), "=r"(r[2]), "=r"(r[3]) : "r"(addr));
}
__device__ __forceinline__ void mma16816(float* d, const uint32_t* a, const uint32_t* b) {
    asm volatile("mma.sync.aligned.m16n8k16.row.col.f32.bf16.bf16.f32 "
        "{%0,%1,%2,%3}, {%4,%5,%6,%7}, {%8,%9}, {%0,%1,%2,%3};"
        : "+f"(d[0]), "+f"(d[1]), "+f"(d[2]), "+f"(d[3])
        : "r"(a[0]), "r"(a[1]), "r"(a[2]), "r"(a[3]), "r"(b[0]), "r"(b[1]));
}

// Grid-wide barrier: monotonic counter (graph-replay safe; GRIDN co-resident).
__device__ __forceinline__ void grid_barrier(int tid) {
    __syncthreads();
    if (tid == 0) {
        __threadfence();
        unsigned int old = atomicAdd(&g_bcount, 1u);
        unsigned int target = (old / GRIDN + 1u) * GRIDN;
        unsigned int v;
        do {
            asm volatile("ld.acquire.gpu.global.u32 %0, [%1];" : "=r"(v) : "l"(&g_bcount));
        } while (v < target);
    }
    __syncthreads();
}

// ---------------------------------------------------------------------------
struct SmemIP { float As[32][64]; float Ws[32][64]; };
// A2 offset = 64*36*4 + 16 = 9232 B -> 2308 floats, mod 32 = 4: banks disjoint
// from A1 ({0,8,16,24} vs {4,12,20,28} for warp row sets {0,2,4,6}+r).
struct SmemG  { float A1[64][36]; float padA[4]; float A2[64][36];
                float W[24][36];  float epi[64][25]; };

// One GRU layer for one step. CTA owns j-range [jb, jb+4): GEMM 64 x 24 x 512
// (cols 0-11: gi {r,z,n} x 4j via Wih & A1; 12-23: gh via Whh & A2) + combine.
// a1mode: 0 = zeros, 1 = embed gather, 2 = pointer.
__device__ __forceinline__ void gates_layer(
    SmemG& s, const int* sTid, int tid, int jb,
    int a1mode, const float* A1g, const float* A2g, const float* embed,
    const float* Wih, const float* Whh,
    const float* bih, const float* bhh,
    const float* hOld, float* hNew,
    __nv_bfloat16* ahi, __nv_bfloat16* alo, int step)
{
    const int mg = tid >> 3;               // 0..31
    const int r0 = mg * 2;                 // rows r0, r0+1
    const int g  = tid & 7;                // 0..7
    const int c0 = g * 3;                  // 0..21
    const float* As = (g < 4) ? &s.A1[0][0] : &s.A2[0][0];
    float acc[2][3] = {};

    // prefetch registers
    float4 pA1[2], pA2[2], pW;
    const int frow = tid >> 3;             // 0..31 (i=0), +32 (i=1)
    const int fc4  = (tid & 7) * 4;        // 0..28
    const int wr   = tid >> 3;             // W row for tid<192
    const int wrr  = (wr < 12) ? wr : wr - 12;
    const float* wbase = (wr < 12) ? Wih : Whh;
    const long  woff = (long)((wrr >> 2) * 512 + jb + (wrr & 3)) * DH + fc4;

    auto fetch = [&](int kt) {
        #pragma unroll
        for (int i = 0; i < 2; i++) {
            int row = frow + i * 32;
            if (a1mode == 0)      pA1[i] = make_float4(0.f, 0.f, 0.f, 0.f);
            else if (a1mode == 1) pA1[i] = *reinterpret_cast<const float4*>(
                                             &embed[(long)sTid[row] * DH + kt + fc4]);
            else                  pA1[i] = *reinterpret_cast<const float4*>(
                                             &A1g[row * DH + kt + fc4]);
            pA2[i] = *reinterpret_cast<const float4*>(&A2g[row * DH + kt + fc4]);
        }
        if (tid < 192)
            pW = *reinterpret_cast<const float4*>(&wbase[woff + kt]);
    };
    auto stage = [&]() {
        #pragma unroll
        for (int i = 0; i < 2; i++) {
            int row = frow + i * 32;
            *reinterpret_cast<float4*>(&s.A1[row][fc4]) = pA1[i];
            *reinterpret_cast<float4*>(&s.A2[row][fc4]) = pA2[i];
        }
        if (tid < 192)
            *reinterpret_cast<float4*>(&s.W[wr][fc4]) = pW;
    };

    fetch(0);
    for (int kt = 0; kt < DH; kt += 32) {
        __syncthreads();                   // prior compute done
        stage();
        __syncthreads();
        if (kt + 32 < DH) fetch(kt + 32);  // hide LDG behind compute
        #pragma unroll
        for (int k = 0; k < 32; k += 4) {
            float4 w0 = *reinterpret_cast<const float4*>(&s.W[c0 + 0][k]);
            float4 w1 = *reinterpret_cast<const float4*>(&s.W[c0 + 1][k]);
            float4 w2 = *reinterpret_cast<const float4*>(&s.W[c0 + 2][k]);
            #pragma unroll
            for (int r = 0; r < 2; r++) {
                float4 a = *reinterpret_cast<const float4*>(&As[(r0 + r) * 36 + k]);
                acc[r][0] += a.x * w0.x + a.y * w0.y + a.z * w0.z + a.w * w0.w;
                acc[r][1] += a.x * w1.x + a.y * w1.y + a.z * w1.z + a.w * w1.w;
                acc[r][2] += a.x * w2.x + a.y * w2.y + a.z * w2.z + a.w * w2.w;
            }
        }
    }

    #pragma unroll
    for (int r = 0; r < 2; r++)
        #pragma unroll
        for (int cc = 0; cc < 3; cc++)
            s.epi[r0 + r][c0 + cc] = acc[r][cc];
    __syncthreads();
    {
        int m = tid >> 2, j = tid & 3, jj = jb + j;
        float gir = s.epi[m][j],      giz = s.epi[m][4 + j],  gin = s.epi[m][8 + j];
        float ghr = s.epi[m][12 + j], ghz = s.epi[m][16 + j], ghn = s.epi[m][20 + j];
        float r = sigmoidf_(gir + bih[jj]       + ghr + bhh[jj]);
        float z = sigmoidf_(giz + bih[512 + jj] + ghz + bhh[512 + jj]);
        float n = tanhf(gin + bih[1024 + jj] + r * (ghn + bhh[1024 + jj]));
        float hnew = (1.f - z) * n + z * hOld[m * DH + jj];
        hNew[m * DH + jj] = hnew;
        if (ahi) {
            int o = (m * NDRAFT + step) * DH + jj;
            __nv_bfloat16 hi = __float2bfloat16(hnew);
            ahi[o] = hi;
            alo[o] = __float2bfloat16(hnew - __bfloat162float(hi));
        }
    }
}

// ---------------------------------------------------------------------------
__global__ __launch_bounds__(256) void gru_fused(
    const float* __restrict__ hidden, const int* __restrict__ tids,
    const float* __restrict__ ip_w,  const float* __restrict__ ip_b,
    const float* __restrict__ w_ih0, const float* __restrict__ w_hh0,
    const float* __restrict__ b_ih0, const float* __restrict__ b_hh0,
    const float* __restrict__ w_ih1, const float* __restrict__ w_hh1,
    const float* __restrict__ b_ih1, const float* __restrict__ b_hh1,
    const float* __restrict__ embed)
{
    __shared__ union { SmemIP ip; SmemG g; } sm;
    __shared__ int sTid[64];
    const int tid = threadIdx.x;
    const int c = blockIdx.x;

    // ---- phase 0: input projection partials (64x64 n-tile, 256-k slice) ----
    {
        const int n0 = (c & 7) * 64;
        const int kbase = (c >> 3) * 256;
        const int ty = tid >> 4, tx = tid & 15;
        float acc[4][4] = {};
        for (int kt = 0; kt < 256; kt += 32) {
            #pragma unroll
            for (int i = 0; i < 2; i++) {
                int f = tid + i * 256;
                int m = f >> 3;
                int kq = (f & 7) << 2;
                float4 va = *reinterpret_cast<const float4*>(&hidden[m * HID + kbase + kt + kq]);
                sm.ip.As[kq + 0][m] = va.x; sm.ip.As[kq + 1][m] = va.y;
                sm.ip.As[kq + 2][m] = va.z; sm.ip.As[kq + 3][m] = va.w;
                float4 vw = *reinterpret_cast<const float4*>(&ip_w[(n0 + m) * HID + kbase + kt + kq]);
                sm.ip.Ws[kq + 0][m] = vw.x; sm.ip.Ws[kq + 1][m] = vw.y;
                sm.ip.Ws[kq + 2][m] = vw.z; sm.ip.Ws[kq + 3][m] = vw.w;
            }
            __syncthreads();
            #pragma unroll
            for (int kk = 0; kk < 32; kk++) {
                float a[4], b[4];
                #pragma unroll
                for (int i = 0; i < 4; i++) { a[i] = sm.ip.As[kk][ty * 4 + i]; b[i] = sm.ip.Ws[kk][tx * 4 + i]; }
                #pragma unroll
                for (int i = 0; i < 4; i++)
                    #pragma unroll
                    for (int j = 0; j < 4; j++) acc[i][j] += a[i] * b[j];
            }
            __syncthreads();
        }
        float* part = g_part + (c >> 3) * (B_ * DH);
        #pragma unroll
        for (int i = 0; i < 4; i++)
            #pragma unroll
            for (int j = 0; j < 4; j++)
                part[(ty * 4 + i) * DH + n0 + tx * 4 + j] = acc[i][j];
    }
    grid_barrier(tid);

    // ---- phase 1: reduce 16 partials + bias ----
    {
        int idx = c * 256 + tid;
        float s = 0.f;
        #pragma unroll
        for (int p = 0; p < 16; p++) s += g_part[p * (B_ * DH) + idx];
        s += ip_b[idx & (DH - 1)];
        g_h[0][0][idx] = s;
        g_h[1][0][idx] = s;
    }
    grid_barrier(tid);

    // ---- 4 draft steps x 2 GRU layers ----
    const int jb = c * 4;
    for (int step = 0; step < NDRAFT; step++) {
        const int p = step & 1;
        if (step > 0 && tid < 64) sTid[tid] = tids[tid * NDRAFT + step - 1];
        __syncthreads();
        gates_layer(sm.g, sTid, tid, jb,
                    (step == 0) ? 0 : 1, nullptr, g_h[0][p], embed,
                    w_ih0, w_hh0, b_ih0, b_hh0,
                    g_h[0][p], g_h[0][1 - p], nullptr, nullptr, step);
        grid_barrier(tid);
        gates_layer(sm.g, sTid, tid, jb,
                    2, g_h[0][1 - p], g_h[1][p], embed,
                    w_ih1, w_hh1, b_ih1, b_hh1,
                    g_h[1][p], g_h[1][1 - p], g_Ahi, g_Alo, step);
        grid_barrier(tid);
    }
}

// ---------------------------------------------------------------------------
// Logits GEMM via mma.sync (bf16 hi/lo 3-MMA split, fp32 accum).
// CTA tile 128(M) x 64(N) x 32(K); 8 warps (2 M x 4 N); warp tile 64x16.
// 2 CTAs/SM. grid (2, 786): m-half pairs adjacent -> B tile L2 reuse.
// ---------------------------------------------------------------------------
#define ROWB 80
#define AHI_OFF(s) ((s) * 10240)
#define ALO_OFF(s) (20480 + (s) * 10240)
#define BHI_OFF(s) (40960 + (s) * 5120)
#define BLO_OFF(s) (51200 + (s) * 5120)
#define LOGITS_SMEM 61440

__global__ __launch_bounds__(256, 2) void logits_mma(const float* __restrict__ W,
                                                     float* __restrict__ out)
{
    extern __shared__ char smem[];
    const uint32_t sbase = smem_to_u32(smem);
    const int tid  = threadIdx.x;
    const int lane = tid & 31;
    const int w    = tid >> 5;
    const int wm   = w >> 2;   // 0..1
    const int wn   = w & 3;    // 0..3
    const int m0   = blockIdx.x * 128;
    const int n0   = blockIdx.y * 64;

    float d[4][2][4];
    #pragma unroll
    for (int i = 0; i < 4; i++)
        #pragma unroll
        for (int j = 0; j < 2; j++)
            #pragma unroll
            for (int q = 0; q < 4; q++) d[i][j][q] = 0.f;

    float4 breg[2];

    auto cpasync_A = [&](int c, int s) {
        const int k0 = c * 32;
        #pragma unroll
        for (int i = 0; i < 2; i++) {
            int idx = tid + i * 256;
            int row = idx >> 2;
            int ch  = idx & 3;
            const __nv_bfloat16* sh = &g_Ahi[(m0 + row) * DH + k0 + ch * 8];
            uint32_t dh = sbase + AHI_OFF(s) + row * ROWB + ch * 16;
            asm volatile("cp.async.ca.shared.global [%0], [%1], 16;" :: "r"(dh), "l"(sh));
            const __nv_bfloat16* sl = &g_Alo[(m0 + row) * DH + k0 + ch * 8];
            uint32_t dl = sbase + ALO_OFF(s) + row * ROWB + ch * 16;
            asm volatile("cp.async.ca.shared.global [%0], [%1], 16;" :: "r"(dl), "l"(sl));
        }
        asm volatile("cp.async.commit_group;" ::: "memory");
    };

    auto ldg_B = [&](int c) {
        const int k0 = c * 32;
        #pragma unroll
        for (int i = 0; i < 2; i++) {
            int idx = tid + i * 256;
            int row = idx >> 3;
            int col = (idx & 7) * 4;
            int vr = n0 + row;
            breg[i] = (vr < VOCAB)
                ? *reinterpret_cast<const float4*>(&W[(long)vr * DH + k0 + col])
                : make_float4(0.f, 0.f, 0.f, 0.f);
        }
    };

    auto sts_B = [&](int s) {
        #pragma unroll
        for (int i = 0; i < 2; i++) {
            int idx = tid + i * 256;
            int row = idx >> 3;
            int col = (idx & 7) * 4;
            float4 v = breg[i];
            __nv_bfloat16 hx = __float2bfloat16(v.x), hy = __float2bfloat16(v.y);
            __nv_bfloat16 hz = __float2bfloat16(v.z), hw = __float2bfloat16(v.w);
            __nv_bfloat16 lx = __float2bfloat16(v.x - __bfloat162float(hx));
            __nv_bfloat16 ly = __float2bfloat16(v.y - __bfloat162float(hy));
            __nv_bfloat16 lz = __float2bfloat16(v.z - __bfloat162float(hz));
            __nv_bfloat16 lw = __float2bfloat16(v.w - __bfloat162float(hw));
            uint2 ph, pl;
            ph.x = pack_bf16x2(hx, hy); ph.y = pack_bf16x2(hz, hw);
            pl.x = pack_bf16x2(lx, ly); pl.y = pack_bf16x2(lz, lw);
            *reinterpret_cast<uint2*>(smem + BHI_OFF(s) + row * ROWB + col * 2) = ph;
            *reinterpret_cast<uint2*>(smem + BLO_OFF(s) + row * ROWB + col * 2) = pl;
        }
    };

    auto compute = [&](int s) {
        #pragma unroll
        for (int ks = 0; ks < 2; ks++) {
            uint32_t ah[4][4], al[4][4];
            #pragma unroll
            for (int mi = 0; mi < 4; mi++) {
                int row = wm * 64 + mi * 16 + (lane & 15);
                int kc  = ks * 32 + (lane >> 4) * 16;
                ldsm4(ah[mi], sbase + AHI_OFF(s) + row * ROWB + kc);
                ldsm4(al[mi], sbase + ALO_OFF(s) + row * ROWB + kc);
            }
            uint32_t bh[2][2], bl[2][2];
            {
                int gq  = lane >> 3;
                int row = wn * 16 + (gq >> 1) * 8 + (lane & 7);
                int kc  = ks * 32 + (gq & 1) * 16;
                ldsm4(&bh[0][0], sbase + BHI_OFF(s) + row * ROWB + kc);
                ldsm4(&bl[0][0], sbase + BLO_OFF(s) + row * ROWB + kc);
            }
            #pragma unroll
            for (int mi = 0; mi < 4; mi++)
                #pragma unroll
                for (int ni = 0; ni < 2; ni++) {
                    mma16816(d[mi][ni], ah[mi], bh[ni]);
                    mma16816(d[mi][ni], ah[mi], bl[ni]);
                    mma16816(d[mi][ni], al[mi], bh[ni]);
                }
        }
    };

    cpasync_A(0, 0);
    ldg_B(0);
    sts_B(0);
    asm volatile("cp.async.wait_group 0;" ::: "memory");
    __syncthreads();

    #pragma unroll 1
    for (int c = 0; c < 16; c++) {
        int s = c & 1;
        if (c + 1 < 16) {
            cpasync_A(c + 1, 1 - s);
            ldg_B(c + 1);
        }
        compute(s);
        if (c + 1 < 16) {
            sts_B(1 - s);
            asm volatile("cp.async.wait_group 0;" ::: "memory");
        }
        __syncthreads();
    }

    const int g  = lane >> 2;
    const int i2 = (lane & 3) * 2;
    #pragma unroll
    for (int mi = 0; mi < 4; mi++) {
        int r0 = m0 + wm * 64 + mi * 16 + g;
        long rb0 = (long)r0 * VOCAB;
        long rb1 = (long)(r0 + 8) * VOCAB;
        #pragma unroll
        for (int ni = 0; ni < 2; ni++) {
            int col = n0 + wn * 16 + ni * 8 + i2;
            if (col < VOCAB) {
                out[rb0 + col] = d[mi][ni][0];
                out[rb1 + col] = d[mi][ni][2];
                if (col + 1 < VOCAB) {
                    out[rb0 + col + 1] = d[mi][ni][1];
                    out[rb1 + col + 1] = d[mi][ni][3];
                }
            }
        }
    }
}

// ---------------------------------------------------------------------------
extern "C" void kernel_launch(void* const* d_in, const int* in_sizes, int n_in,
                              void* d_out, int out_size)
{
    const float* hidden = (const float*)d_in[0];
    const int*   tids   = (const int*)  d_in[1];
    const float* ip_w   = (const float*)d_in[2];
    const float* ip_b   = (const float*)d_in[3];
    const float* w_ih0  = (const float*)d_in[4];
    const float* w_hh0  = (const float*)d_in[5];
    const float* b_ih0  = (const float*)d_in[6];
    const float* b_hh0  = (const float*)d_in[7];
    const float* w_ih1  = (const float*)d_in[8];
    const float* w_hh1  = (const float*)d_in[9];
    const float* b_ih1  = (const float*)d_in[10];
    const float* b_hh1  = (const float*)d_in[11];
    const float* embed  = (const float*)d_in[12];
    const float* out_w  = (const float*)d_in[13];
    float* out = (float*)d_out;

    cudaFuncSetAttribute(logits_mma, cudaFuncAttributeMaxDynamicSharedMemorySize, LOGITS_SMEM);

    gru_fused<<<GRIDN, 256>>>(hidden, tids, ip_w, ip_b,
                              w_ih0, w_hh0, b_ih0, b_hh0,
                              w_ih1, w_hh1, b_ih1, b_hh1, embed);

    logits_mma<<<dim3(2, (VOCAB + 63) / 64), 256, LOGITS_SMEM>>>(out_w, out);
}